// round 4
// baseline (speedup 1.0000x reference)
#include <cuda_runtime.h>
#include <cstdint>
#include <cstddef>

#define NN 100000
#define NE 640000

typedef unsigned long long u64t;

__device__ float g_pre[(size_t)NN * 128];   // [n][0:64]=x@Wa+eb1, [64:128]=x@Wb
__device__ float g_agg[(size_t)NN * 128];   // scatter-sum of e2
__device__ float g_cnt[NN];                 // edge counts per dest node
__device__ int   g_is64;                    // edge_index dtype flag (1 = int64)

// ---------- packed f32x2 helpers ----------
__device__ __forceinline__ u64t pk2(float lo, float hi) {
    u64t r; asm("mov.b64 %0,{%1,%2};" : "=l"(r) : "f"(lo), "f"(hi)); return r;
}
__device__ __forceinline__ float2 upk(u64t v) {
    float2 r; asm("mov.b64 {%0,%1},%2;" : "=f"(r.x), "=f"(r.y) : "l"(v)); return r;
}
__device__ __forceinline__ void fma2(u64t& d, u64t a, u64t b) {
    asm("fma.rn.f32x2 %0,%1,%2,%0;" : "+l"(d) : "l"(a), "l"(b));
}

// ------------------ detect edge_index element width -------------------
__global__ void k_detect(const unsigned int* __restrict__ w) {
    unsigned int any = 0;
    for (int i = threadIdx.x; i < 1024; i += 32) any |= w[2 * i + 1];
#pragma unroll
    for (int o = 16; o > 0; o >>= 1) any |= __shfl_xor_sync(0xffffffffu, any, o);
    if (threadIdx.x == 0) g_is64 = (any == 0) ? 1 : 0;
}

// ---------------------------- zero scratch ----------------------------
__global__ void k_zero() {
    size_t i = (size_t)blockIdx.x * blockDim.x + threadIdx.x;
    size_t stride = (size_t)gridDim.x * blockDim.x;
    float4* a4 = (float4*)g_agg;
    const size_t n4 = (size_t)NN * 32;
    for (size_t j = i; j < n4; j += stride) a4[j] = make_float4(0.f, 0.f, 0.f, 0.f);
    for (size_t j = i; j < (size_t)NN; j += stride) g_cnt[j] = 0.f;
}

// ------------- kernel 1: pre[n] = x @ [Wa|Wb] (+eb1 on Wa half), 512 thr --------
__global__ void __launch_bounds__(512, 1) k_pre(
    const float* __restrict__ x, const float* __restrict__ ew1,
    const float* __restrict__ eb1) {
    extern __shared__ float sm[];
    float* sW = sm;             // 16384
    float* sX = sm + 16384;     // 128*129 = 16512
    const int tid = threadIdx.x;
    const int n0 = blockIdx.x * 128;

    for (int idx = tid; idx < 16384; idx += 512) {
        int k = idx >> 7, j = idx & 127;
        sW[idx] = (j < 64) ? __ldg(ew1 + k * 64 + j)
                           : __ldg(ew1 + (128 + k) * 64 + (j - 64));
    }
#pragma unroll
    for (int it = 0; it < 8; ++it) {
        int idx = tid + it * 512;
        int r = idx >> 5, q = idx & 31;
        int n = n0 + r;
        float4 v = make_float4(0.f, 0.f, 0.f, 0.f);
        if (n < NN) v = __ldg((const float4*)(x + (size_t)n * 128) + q);
        float* dst = sX + r * 129 + q * 4;
        dst[0] = v.x; dst[1] = v.y; dst[2] = v.z; dst[3] = v.w;
    }
    __syncthreads();

    const int tx = tid & 31, w = tid >> 5;
    const int c0 = (w >> 1) * 16;   // 8 col groups of 16 cols (8 u64)
    const int half = w & 1;         // 2 row groups
    u64t acc[2][8];
#pragma unroll
    for (int i = 0; i < 2; i++)
#pragma unroll
        for (int p = 0; p < 8; p++) acc[i][p] = 0ull;

    const float* er[2];
#pragma unroll
    for (int i = 0; i < 2; i++) er[i] = sX + (tx + 32 * (2 * i + half)) * 129;

#pragma unroll 4
    for (int k = 0; k < 128; k++) {
        u64t b[8];
        const u64t* bp = (const u64t*)(sW + (k << 7) + c0);
#pragma unroll
        for (int p = 0; p < 8; p++) b[p] = bp[p];
#pragma unroll
        for (int i = 0; i < 2; i++) {
            float a = er[i][k];
            u64t ap = pk2(a, a);
#pragma unroll
            for (int p = 0; p < 8; p++) fma2(acc[i][p], ap, b[p]);
        }
    }
#pragma unroll
    for (int i = 0; i < 2; i++) {
        int n = n0 + tx + 32 * (2 * i + half);
        if (n >= NN) continue;
        float* dst = g_pre + (size_t)n * 128 + c0;
#pragma unroll
        for (int p = 0; p < 8; p++) {
            float2 v = upk(acc[i][p]);
            int j = c0 + 2 * p;
            if (j < 64)     v.x += __ldg(eb1 + j);
            if (j + 1 < 64) v.y += __ldg(eb1 + j + 1);
            dst[2 * p] = v.x; dst[2 * p + 1] = v.y;
        }
    }
}

// ------------------------------- kernel 2: edges (512 thr) ----------------------
__global__ void __launch_bounds__(512, 1) k_edge(
    const float* __restrict__ ea, const void* __restrict__ ei_raw,
    const float* __restrict__ ew1, const float* __restrict__ ew2,
    const float* __restrict__ eb2, const float* __restrict__ ne_g,
    const float* __restrict__ ne_b, float* __restrict__ eout) {
    extern __shared__ float sm[];
    float* sW1  = sm;                    // 128*64  = 8192
    float* sE   = sm + 8192;             // 128*129 = 16512
    float* sPAB = sm + 24704;            // 128*65  = 8320 (H written in place)
    float* sW2  = sm + 33024;            // 64*128  = 8192
    int*   sRow = (int*)(sm + 41216);    // 128
    int*   sCol = sRow + 128;            // 128
    float* sEB2 = sm + 41472;            // 128
    const int tid = threadIdx.x;
    const int e0 = blockIdx.x * 128;

    if (tid < 128) {
        int e = e0 + tid;
        int r, c;
        if (g_is64) {
            const long long* p = (const long long*)ei_raw;
            r = (int)__ldg(p + e);
            c = (int)__ldg(p + (size_t)NE + e);
        } else {
            const int* p = (const int*)ei_raw;
            r = __ldg(p + e);
            c = __ldg(p + (size_t)NE + e);
        }
        sRow[tid] = min(max(r, 0), NN - 1);
        sCol[tid] = min(max(c, 0), NN - 1);
        sEB2[tid] = __ldg(eb2 + tid);
    }
    for (int idx = tid; idx < 8192; idx += 512)
        sW1[idx] = __ldg(ew1 + ((256 + (idx >> 6)) << 6) + (idx & 63));
    for (int idx = tid; idx < 8192; idx += 512)
        sW2[idx] = __ldg(ew2 + idx);
#pragma unroll
    for (int it = 0; it < 8; ++it) {
        int idx = tid + it * 512;
        int r = idx >> 5, q = idx & 31;
        float4 v = __ldg((const float4*)(ea + (size_t)(e0 + r) * 128) + q);
        float* dst = sE + r * 129 + q * 4;
        dst[0] = v.x; dst[1] = v.y; dst[2] = v.z; dst[3] = v.w;
    }
    __syncthreads();
    // gather pa[row] + pb[col]
#pragma unroll
    for (int it = 0; it < 4; ++it) {
        int idx = tid + it * 512;
        int el = idx >> 4, q = idx & 15;
        int rn = sRow[el], cn = sCol[el];
        float4 va = __ldg((const float4*)(g_pre + (size_t)rn * 128) + q);
        float4 vb = __ldg((const float4*)(g_pre + (size_t)cn * 128) + 16 + q);
        float* dst = sPAB + el * 65 + q * 4;
        dst[0] = va.x + vb.x; dst[1] = va.y + vb.y;
        dst[2] = va.z + vb.z; dst[3] = va.w + vb.w;
    }
    __syncthreads();

    const int tx = tid & 31, w = tid >> 5;
    const int half = w & 1;
    // stage 1: H[128][64] = relu(E@We + PAB), H overwrites PAB in place
    {
        const int c0 = (w >> 1) * 8;    // 8 col groups of 8 cols (4 u64)
        u64t acc[2][4];
#pragma unroll
        for (int i = 0; i < 2; i++)
#pragma unroll
            for (int p = 0; p < 4; p++) acc[i][p] = 0ull;
        const float* er[2];
#pragma unroll
        for (int i = 0; i < 2; i++) er[i] = sE + (tx + 32 * (2 * i + half)) * 129;
#pragma unroll 4
        for (int k = 0; k < 128; k++) {
            const u64t* bp = (const u64t*)(sW1 + (k << 6) + c0);
            u64t b0 = bp[0], b1 = bp[1], b2 = bp[2], b3 = bp[3];
#pragma unroll
            for (int i = 0; i < 2; i++) {
                float a = er[i][k];
                u64t ap = pk2(a, a);
                fma2(acc[i][0], ap, b0); fma2(acc[i][1], ap, b1);
                fma2(acc[i][2], ap, b2); fma2(acc[i][3], ap, b3);
            }
        }
#pragma unroll
        for (int i = 0; i < 2; i++) {
            int r = tx + 32 * (2 * i + half);
            float* hd = sPAB + r * 65 + c0;    // read pab, write H same cells
#pragma unroll
            for (int p = 0; p < 4; p++) {
                float2 v = upk(acc[i][p]);
                float p0 = hd[2 * p], p1 = hd[2 * p + 1];
                hd[2 * p]     = fmaxf(v.x + p0, 0.f);
                hd[2 * p + 1] = fmaxf(v.y + p1, 0.f);
            }
        }
    }
    __syncthreads();
    // stage 2: e2 = H@ew2 + eb2 + e  (written back into sE, same-thread cells)
    {
        const int c1 = (w >> 1) * 16;   // 8 col groups of 16 cols (8 u64)
        u64t acc[2][8];
#pragma unroll
        for (int i = 0; i < 2; i++)
#pragma unroll
            for (int p = 0; p < 8; p++) acc[i][p] = 0ull;
        const float* hr[2];
#pragma unroll
        for (int i = 0; i < 2; i++) hr[i] = sPAB + (tx + 32 * (2 * i + half)) * 65;
#pragma unroll 2
        for (int k = 0; k < 64; k++) {
            u64t b[8];
            const u64t* bp = (const u64t*)(sW2 + (k << 7) + c1);
#pragma unroll
            for (int p = 0; p < 8; p++) b[p] = bp[p];
#pragma unroll
            for (int i = 0; i < 2; i++) {
                float a = hr[i][k];
                u64t ap = pk2(a, a);
#pragma unroll
                for (int p = 0; p < 8; p++) fma2(acc[i][p], ap, b[p]);
            }
        }
#pragma unroll
        for (int i = 0; i < 2; i++) {
            int r = tx + 32 * (2 * i + half);
            float* erow = sE + r * 129 + c1;
#pragma unroll
            for (int p = 0; p < 8; p++) {
                float2 v = upk(acc[i][p]);
                int j = c1 + 2 * p;
                erow[2 * p]     += v.x + sEB2[j];
                erow[2 * p + 1] += v.y + sEB2[j + 1];
            }
        }
    }
    __syncthreads();
    // LayerNorm + vector-atomic scatter (4 threads per edge row)
    {
        const int r = tid >> 2, qtr = tid & 3;
        const float* rowp = sE + r * 129 + qtr * 32;
        float s = 0.f, s2 = 0.f;
#pragma unroll 8
        for (int k = 0; k < 32; k++) { float t = rowp[k]; s += t; s2 = fmaf(t, t, s2); }
        s  += __shfl_xor_sync(0xffffffffu, s, 1);
        s2 += __shfl_xor_sync(0xffffffffu, s2, 1);
        s  += __shfl_xor_sync(0xffffffffu, s, 2);
        s2 += __shfl_xor_sync(0xffffffffu, s2, 2);
        const float mu  = s * 0.0078125f;
        const float var = fmaf(-mu, mu, s2 * 0.0078125f);
        const float rstd = rsqrtf(var + 1e-5f);
        const int e = e0 + r;
        float* outp = eout + (size_t)e * 128 + qtr * 32;
        const int cn = sCol[r];
        float4* aggp = (float4*)(g_agg + (size_t)cn * 128 + qtr * 32);
#pragma unroll
        for (int q = 0; q < 8; q++) {
            float v0 = rowp[4 * q], v1 = rowp[4 * q + 1];
            float v2 = rowp[4 * q + 2], v3 = rowp[4 * q + 3];
            atomicAdd(aggp + q, make_float4(v0, v1, v2, v3));
            int j = qtr * 32 + 4 * q;
            float4 o;
            o.x = fmaf((v0 - mu) * rstd, __ldg(ne_g + j),     __ldg(ne_b + j));
            o.y = fmaf((v1 - mu) * rstd, __ldg(ne_g + j + 1), __ldg(ne_b + j + 1));
            o.z = fmaf((v2 - mu) * rstd, __ldg(ne_g + j + 2), __ldg(ne_b + j + 2));
            o.w = fmaf((v3 - mu) * rstd, __ldg(ne_g + j + 3), __ldg(ne_b + j + 3));
            *(float4*)(outp + 4 * q) = o;
        }
        if (qtr == 0) atomicAdd(g_cnt + cn, 1.0f);
    }
}

// ------------------------------- kernel 3: nodes (512 thr) ----------------------
__global__ void __launch_bounds__(512, 1) k_node(
    const float* __restrict__ x, const float* __restrict__ nw1,
    const float* __restrict__ nb1, const float* __restrict__ nw2,
    const float* __restrict__ nb2, const float* __restrict__ nx_g,
    const float* __restrict__ nx_b, float* __restrict__ xout) {
    extern __shared__ float sm[];
    float* sX   = sm;            // 128*129 = 16512
    float* sA   = sm + 16512;    // 128*129 = 16512
    float* sW1h = sm + 33024;    // 128*64  = 8192 (reloaded between passes)
    float* sH   = sm + 41216;    // 128*65  = 8320
    float* sW2  = sm + 49536;    // 64*128  = 8192
    float* sNB2 = sm + 57728;    // 128
    const int tid = threadIdx.x;
    const int n0 = blockIdx.x * 128;

#pragma unroll
    for (int it = 0; it < 8; ++it) {
        int idx = tid + it * 512;
        int r = idx >> 5, q = idx & 31;
        int n = n0 + r;
        float4 v = make_float4(0.f, 0.f, 0.f, 0.f);
        float4 w4 = make_float4(0.f, 0.f, 0.f, 0.f);
        if (n < NN) {
            v = __ldg((const float4*)(x + (size_t)n * 128) + q);
            float c = g_cnt[n];
            float inv = 1.0f / fmaxf(c, 1.0f);
            float4 a = *((const float4*)(g_agg + (size_t)n * 128) + q);
            w4 = make_float4(a.x * inv, a.y * inv, a.z * inv, a.w * inv);
        }
        float* dx = sX + r * 129 + q * 4;
        dx[0] = v.x; dx[1] = v.y; dx[2] = v.z; dx[3] = v.w;
        float* da = sA + r * 129 + q * 4;
        da[0] = w4.x; da[1] = w4.y; da[2] = w4.z; da[3] = w4.w;
    }
    for (int idx = tid; idx < 8192; idx += 512) sW1h[idx] = __ldg(nw1 + idx);
    for (int idx = tid; idx < 8192; idx += 512) sW2[idx] = __ldg(nw2 + idx);
    if (tid < 128) sNB2[tid] = __ldg(nb2 + tid);
    __syncthreads();

    const int tx = tid & 31, w = tid >> 5;
    const int half = w & 1;
    const int c0 = (w >> 1) * 8;
    u64t acc[2][4];
#pragma unroll
    for (int i = 0; i < 2; i++)
#pragma unroll
        for (int p = 0; p < 4; p++) acc[i][p] = 0ull;
    {
        const float* er[2];
#pragma unroll
        for (int i = 0; i < 2; i++) er[i] = sX + (tx + 32 * (2 * i + half)) * 129;
#pragma unroll 4
        for (int k = 0; k < 128; k++) {
            const u64t* bp = (const u64t*)(sW1h + (k << 6) + c0);
            u64t b0 = bp[0], b1 = bp[1], b2 = bp[2], b3 = bp[3];
#pragma unroll
            for (int i = 0; i < 2; i++) {
                float a = er[i][k];
                u64t ap = pk2(a, a);
                fma2(acc[i][0], ap, b0); fma2(acc[i][1], ap, b1);
                fma2(acc[i][2], ap, b2); fma2(acc[i][3], ap, b3);
            }
        }
    }
    __syncthreads();
    for (int idx = tid; idx < 8192; idx += 512) sW1h[idx] = __ldg(nw1 + 8192 + idx);
    __syncthreads();
    {
        const float* er[2];
#pragma unroll
        for (int i = 0; i < 2; i++) er[i] = sA + (tx + 32 * (2 * i + half)) * 129;
#pragma unroll 4
        for (int k = 0; k < 128; k++) {
            const u64t* bp = (const u64t*)(sW1h + (k << 6) + c0);
            u64t b0 = bp[0], b1 = bp[1], b2 = bp[2], b3 = bp[3];
#pragma unroll
            for (int i = 0; i < 2; i++) {
                float a = er[i][k];
                u64t ap = pk2(a, a);
                fma2(acc[i][0], ap, b0); fma2(acc[i][1], ap, b1);
                fma2(acc[i][2], ap, b2); fma2(acc[i][3], ap, b3);
            }
        }
    }
#pragma unroll
    for (int i = 0; i < 2; i++) {
        int r = tx + 32 * (2 * i + half);
        float* hd = sH + r * 65 + c0;
#pragma unroll
        for (int p = 0; p < 4; p++) {
            float2 v = upk(acc[i][p]);
            hd[2 * p]     = fmaxf(v.x + __ldg(nb1 + c0 + 2 * p), 0.f);
            hd[2 * p + 1] = fmaxf(v.y + __ldg(nb1 + c0 + 2 * p + 1), 0.f);
        }
    }
    __syncthreads();
    // stage 2
    {
        const int c1 = (w >> 1) * 16;
        u64t acc2[2][8];
#pragma unroll
        for (int i = 0; i < 2; i++)
#pragma unroll
            for (int p = 0; p < 8; p++) acc2[i][p] = 0ull;
        const float* hr[2];
#pragma unroll
        for (int i = 0; i < 2; i++) hr[i] = sH + (tx + 32 * (2 * i + half)) * 65;
#pragma unroll 2
        for (int k = 0; k < 64; k++) {
            u64t b[8];
            const u64t* bp = (const u64t*)(sW2 + (k << 7) + c1);
#pragma unroll
            for (int p = 0; p < 8; p++) b[p] = bp[p];
#pragma unroll
            for (int i = 0; i < 2; i++) {
                float a = hr[i][k];
                u64t ap = pk2(a, a);
#pragma unroll
                for (int p = 0; p < 8; p++) fma2(acc2[i][p], ap, b[p]);
            }
        }
#pragma unroll
        for (int i = 0; i < 2; i++) {
            int r = tx + 32 * (2 * i + half);
            float* xrow = sX + r * 129 + c1;
#pragma unroll
            for (int p = 0; p < 8; p++) {
                float2 v = upk(acc2[i][p]);
                int j = c1 + 2 * p;
                xrow[2 * p]     += v.x + sNB2[j];
                xrow[2 * p + 1] += v.y + sNB2[j + 1];
            }
        }
    }
    __syncthreads();
    // LayerNorm -> x_out (4 threads per row)
    {
        const int r = tid >> 2, qtr = tid & 3;
        const float* rowp = sX + r * 129 + qtr * 32;
        float s = 0.f, s2 = 0.f;
#pragma unroll 8
        for (int k = 0; k < 32; k++) { float t = rowp[k]; s += t; s2 = fmaf(t, t, s2); }
        s  += __shfl_xor_sync(0xffffffffu, s, 1);
        s2 += __shfl_xor_sync(0xffffffffu, s2, 1);
        s  += __shfl_xor_sync(0xffffffffu, s, 2);
        s2 += __shfl_xor_sync(0xffffffffu, s2, 2);
        const float mu  = s * 0.0078125f;
        const float var = fmaf(-mu, mu, s2 * 0.0078125f);
        const float rstd = rsqrtf(var + 1e-5f);
        const int n = n0 + r;
        if (n < NN) {
            float* outp = xout + (size_t)n * 128 + qtr * 32;
#pragma unroll
            for (int q = 0; q < 8; q++) {
                float v0 = rowp[4 * q], v1 = rowp[4 * q + 1];
                float v2 = rowp[4 * q + 2], v3 = rowp[4 * q + 3];
                int j = qtr * 32 + 4 * q;
                float4 o;
                o.x = fmaf((v0 - mu) * rstd, __ldg(nx_g + j),     __ldg(nx_b + j));
                o.y = fmaf((v1 - mu) * rstd, __ldg(nx_g + j + 1), __ldg(nx_b + j + 1));
                o.z = fmaf((v2 - mu) * rstd, __ldg(nx_g + j + 2), __ldg(nx_b + j + 2));
                o.w = fmaf((v3 - mu) * rstd, __ldg(nx_g + j + 3), __ldg(nx_b + j + 3));
                *(float4*)(outp + 4 * q) = o;
            }
        }
    }
}

// --------------------------------- launch ---------------------------------------
extern "C" void kernel_launch(void* const* d_in, const int* in_sizes, int n_in,
                              void* d_out, int out_size) {
    const float* x   = (const float*)d_in[0];
    const void*  ei  = d_in[1];               // int32 or int64 — detected on device
    const float* ea  = (const float*)d_in[2];
    const float* ew1 = (const float*)d_in[4];
    const float* eb1 = (const float*)d_in[5];
    const float* ew2 = (const float*)d_in[6];
    const float* eb2 = (const float*)d_in[7];
    const float* nw1 = (const float*)d_in[8];
    const float* nb1 = (const float*)d_in[9];
    const float* nw2 = (const float*)d_in[10];
    const float* nb2 = (const float*)d_in[11];
    const float* nxg = (const float*)d_in[12];
    const float* nxb = (const float*)d_in[13];
    const float* neg_ = (const float*)d_in[14];
    const float* neb_ = (const float*)d_in[15];
    float* xout = (float*)d_out;
    float* eout = xout + (size_t)NN * 128;

    const int SM_PRE  = 131584;              // (16384+16512)*4
    const int SM_EDGE = 41216 * 4 + 1536;    // 166400
    const int SM_NODE = 57728 * 4 + 512;     // 231424
    cudaFuncSetAttribute(k_pre,  cudaFuncAttributeMaxDynamicSharedMemorySize, SM_PRE);
    cudaFuncSetAttribute(k_edge, cudaFuncAttributeMaxDynamicSharedMemorySize, SM_EDGE);
    cudaFuncSetAttribute(k_node, cudaFuncAttributeMaxDynamicSharedMemorySize, SM_NODE);

    k_detect<<<1, 32>>>((const unsigned int*)ei);
    k_zero<<<1024, 256>>>();
    k_pre <<<(NN + 127) / 128, 512, SM_PRE>>>(x, ew1, eb1);
    k_edge<<<NE / 128, 512, SM_EDGE>>>(ea, ei, ew1, ew2, eb2, neg_, neb_, eout);
    k_node<<<(NN + 127) / 128, 512, SM_NODE>>>(x, nw1, nb1, nw2, nb2, nxg, nxb, xout);
}

// round 5
// speedup vs baseline: 1.2448x; 1.2448x over previous
#include <cuda_runtime.h>
#include <cstdint>
#include <cstddef>

#define NN 100000
#define NE 640000

typedef unsigned long long u64t;

__device__ float g_pre[(size_t)NN * 128];   // [n][0:64]=x@Wa+eb1, [64:128]=x@Wb
__device__ float g_agg[(size_t)NN * 128];   // scatter-sum of e2
__device__ float g_cnt[NN];                 // edge counts per dest node
__device__ int   g_is64;                    // edge_index dtype flag (1 = int64)

// ---------- packed f32x2 helpers ----------
__device__ __forceinline__ u64t pk2(float lo, float hi) {
    u64t r; asm("mov.b64 %0,{%1,%2};" : "=l"(r) : "f"(lo), "f"(hi)); return r;
}
__device__ __forceinline__ float2 upk(u64t v) {
    float2 r; asm("mov.b64 {%0,%1},%2;" : "=f"(r.x), "=f"(r.y) : "l"(v)); return r;
}
__device__ __forceinline__ void fma2(u64t& d, u64t a, u64t b) {
    asm("fma.rn.f32x2 %0,%1,%2,%0;" : "+l"(d) : "l"(a), "l"(b));
}

// ------------------ detect edge_index element width -------------------
__global__ void k_detect(const unsigned int* __restrict__ w) {
    unsigned int any = 0;
    for (int i = threadIdx.x; i < 1024; i += 32) any |= w[2 * i + 1];
#pragma unroll
    for (int o = 16; o > 0; o >>= 1) any |= __shfl_xor_sync(0xffffffffu, any, o);
    if (threadIdx.x == 0) g_is64 = (any == 0) ? 1 : 0;
}

// ---------------------------- zero scratch ----------------------------
__global__ void k_zero() {
    size_t i = (size_t)blockIdx.x * blockDim.x + threadIdx.x;
    size_t stride = (size_t)gridDim.x * blockDim.x;
    float4* a4 = (float4*)g_agg;
    const size_t n4 = (size_t)NN * 32;
    for (size_t j = i; j < n4; j += stride) a4[j] = make_float4(0.f, 0.f, 0.f, 0.f);
    for (size_t j = i; j < (size_t)NN; j += stride) g_cnt[j] = 0.f;
}

// ------------- kernel 1: pre[n] = x @ [Wa|Wb] (+eb1 on Wa half) — R3 version ----
__global__ void __launch_bounds__(256, 1) k_pre(
    const float* __restrict__ x, const float* __restrict__ ew1,
    const float* __restrict__ eb1) {
    extern __shared__ float sm[];
    float* sW = sm;             // 16384
    float* sX = sm + 16384;     // 128*129 = 16512
    const int tid = threadIdx.x;
    const int n0 = blockIdx.x * 128;

    for (int idx = tid; idx < 16384; idx += 256) {
        int k = idx >> 7, j = idx & 127;
        sW[idx] = (j < 64) ? __ldg(ew1 + k * 64 + j)
                           : __ldg(ew1 + (128 + k) * 64 + (j - 64));
    }
#pragma unroll
    for (int it = 0; it < 16; ++it) {
        int idx = tid + it * 256;
        int r = idx >> 5, q = idx & 31;
        int n = n0 + r;
        float4 v = make_float4(0.f, 0.f, 0.f, 0.f);
        if (n < NN) v = __ldg((const float4*)(x + (size_t)n * 128) + q);
        float* dst = sX + r * 129 + q * 4;
        dst[0] = v.x; dst[1] = v.y; dst[2] = v.z; dst[3] = v.w;
    }
    __syncthreads();

    const int tx = tid & 31, ty = tid >> 5;
    const int c0 = ty * 16;
    u64t acc[4][8];
#pragma unroll
    for (int i = 0; i < 4; i++)
#pragma unroll
        for (int p = 0; p < 8; p++) acc[i][p] = 0ull;

    const float* er[4];
#pragma unroll
    for (int i = 0; i < 4; i++) er[i] = sX + (tx + 32 * i) * 129;

#pragma unroll 4
    for (int k = 0; k < 128; k++) {
        u64t b[8];
        const u64t* bp = (const u64t*)(sW + (k << 7) + c0);
#pragma unroll
        for (int p = 0; p < 8; p++) b[p] = bp[p];
#pragma unroll
        for (int i = 0; i < 4; i++) {
            float a = er[i][k];
            u64t ap = pk2(a, a);
#pragma unroll
            for (int p = 0; p < 8; p++) fma2(acc[i][p], ap, b[p]);
        }
    }
#pragma unroll
    for (int i = 0; i < 4; i++) {
        int n = n0 + tx + 32 * i;
        if (n >= NN) continue;
        float* dst = g_pre + (size_t)n * 128 + c0;
#pragma unroll
        for (int p = 0; p < 8; p++) {
            float2 v = upk(acc[i][p]);
            int j = c0 + 2 * p;
            if (j < 64)     v.x += __ldg(eb1 + j);
            if (j + 1 < 64) v.y += __ldg(eb1 + j + 1);
            dst[2 * p] = v.x; dst[2 * p + 1] = v.y;
        }
    }
}

// ------------------------------- kernel 2: edges (256 thr, LDS.128 B loads) -----
__global__ void __launch_bounds__(256, 1) k_edge(
    const float* __restrict__ ea, const void* __restrict__ ei_raw,
    const float* __restrict__ ew1, const float* __restrict__ ew2,
    const float* __restrict__ eb2, const float* __restrict__ ne_g,
    const float* __restrict__ ne_b, float* __restrict__ eout) {
    extern __shared__ float sm[];
    float* sW1  = sm;                    // 128*64  = 8192
    float* sE   = sm + 8192;             // 128*129 = 16512
    float* sPAB = sm + 24704;            // 128*65  = 8320 (H written in place)
    float* sW2  = sm + 33024;            // 64*128  = 8192
    int*   sRow = (int*)(sm + 41216);    // 128
    int*   sCol = sRow + 128;            // 128
    float* sEB2 = sm + 41472;            // 128
    const int tid = threadIdx.x;
    const int e0 = blockIdx.x * 128;
    const int is64 = g_is64;

    // indices for the LN/scatter epilogue (gather reads them directly from gmem)
    if (tid < 128) {
        int e = e0 + tid;
        int r, c;
        if (is64) {
            const long long* p = (const long long*)ei_raw;
            r = (int)__ldg(p + e);
            c = (int)__ldg(p + (size_t)NE + e);
        } else {
            const int* p = (const int*)ei_raw;
            r = __ldg(p + e);
            c = __ldg(p + (size_t)NE + e);
        }
        sRow[tid] = min(max(r, 0), NN - 1);
        sCol[tid] = min(max(c, 0), NN - 1);
        sEB2[tid] = __ldg(eb2 + tid);
    }
    // gather pa[row]+pb[col] — indices read directly so the L2-latency loads
    // overlap the sE fill and weight staging below (no barrier in between).
#pragma unroll
    for (int it = 0; it < 8; ++it) {
        int idx = tid + it * 256;
        int el = idx >> 4, q = idx & 15;
        int e = e0 + el;
        int rn, cn;
        if (is64) {
            const long long* p = (const long long*)ei_raw;
            rn = (int)__ldg(p + e);
            cn = (int)__ldg(p + (size_t)NE + e);
        } else {
            const int* p = (const int*)ei_raw;
            rn = __ldg(p + e);
            cn = __ldg(p + (size_t)NE + e);
        }
        rn = min(max(rn, 0), NN - 1);
        cn = min(max(cn, 0), NN - 1);
        float4 va = __ldg((const float4*)(g_pre + (size_t)rn * 128) + q);
        float4 vb = __ldg((const float4*)(g_pre + (size_t)cn * 128) + 16 + q);
        float* dst = sPAB + el * 65 + q * 4;
        dst[0] = va.x + vb.x; dst[1] = va.y + vb.y;
        dst[2] = va.z + vb.z; dst[3] = va.w + vb.w;
    }
    for (int idx = tid; idx < 8192; idx += 256)
        sW1[idx] = __ldg(ew1 + ((256 + (idx >> 6)) << 6) + (idx & 63));
    for (int idx = tid; idx < 8192; idx += 256)
        sW2[idx] = __ldg(ew2 + idx);
#pragma unroll
    for (int it = 0; it < 16; ++it) {
        int idx = tid + it * 256;
        int r = idx >> 5, q = idx & 31;
        float4 v = __ldg((const float4*)(ea + (size_t)(e0 + r) * 128) + q);
        float* dst = sE + r * 129 + q * 4;
        dst[0] = v.x; dst[1] = v.y; dst[2] = v.z; dst[3] = v.w;
    }
    __syncthreads();

    const int tx = tid & 31, ty = tid >> 5;
    // stage 1: H[128][64] = relu(E@We + PAB), H overwrites PAB in place
    {
        const int c0 = ty * 8;          // 8 col groups of 8 cols (2 ull2)
        u64t acc[4][4];
#pragma unroll
        for (int i = 0; i < 4; i++)
#pragma unroll
            for (int p = 0; p < 4; p++) acc[i][p] = 0ull;
        const float* er[4];
#pragma unroll
        for (int i = 0; i < 4; i++) er[i] = sE + (tx + 32 * i) * 129;
#pragma unroll 8
        for (int k0 = 0; k0 < 128; k0 += 4) {
            float av[4][4];
#pragma unroll
            for (int i = 0; i < 4; i++)
#pragma unroll
                for (int kk = 0; kk < 4; kk++) av[i][kk] = er[i][k0 + kk];
#pragma unroll
            for (int kk = 0; kk < 4; kk++) {
                const ulonglong2* bp = (const ulonglong2*)(sW1 + ((k0 + kk) << 6) + c0);
                ulonglong2 b01 = bp[0], b23 = bp[1];
#pragma unroll
                for (int i = 0; i < 4; i++) {
                    u64t ap = pk2(av[i][kk], av[i][kk]);
                    fma2(acc[i][0], ap, b01.x); fma2(acc[i][1], ap, b01.y);
                    fma2(acc[i][2], ap, b23.x); fma2(acc[i][3], ap, b23.y);
                }
            }
        }
#pragma unroll
        for (int i = 0; i < 4; i++) {
            int r = tx + 32 * i;
            float* hd = sPAB + r * 65 + c0;    // read pab, write H same cells
#pragma unroll
            for (int p = 0; p < 4; p++) {
                float2 v = upk(acc[i][p]);
                float p0 = hd[2 * p], p1 = hd[2 * p + 1];
                hd[2 * p]     = fmaxf(v.x + p0, 0.f);
                hd[2 * p + 1] = fmaxf(v.y + p1, 0.f);
            }
        }
    }
    __syncthreads();
    // stage 2: e2 = H@ew2 + eb2 + e  (written back into sE, same-thread cells)
    {
        const int c1 = ty * 16;         // 8 col groups of 16 cols (4 ull2)
        u64t acc[4][8];
#pragma unroll
        for (int i = 0; i < 4; i++)
#pragma unroll
            for (int p = 0; p < 8; p++) acc[i][p] = 0ull;
        const float* hr[4];
#pragma unroll
        for (int i = 0; i < 4; i++) hr[i] = sPAB + (tx + 32 * i) * 65;
#pragma unroll 8
        for (int k0 = 0; k0 < 64; k0 += 2) {
            float av[4][2];
#pragma unroll
            for (int i = 0; i < 4; i++) {
                av[i][0] = hr[i][k0];
                av[i][1] = hr[i][k0 + 1];
            }
#pragma unroll
            for (int kk = 0; kk < 2; kk++) {
                const ulonglong2* bp = (const ulonglong2*)(sW2 + ((k0 + kk) << 7) + c1);
                ulonglong2 b01 = bp[0], b23 = bp[1], b45 = bp[2], b67 = bp[3];
#pragma unroll
                for (int i = 0; i < 4; i++) {
                    u64t ap = pk2(av[i][kk], av[i][kk]);
                    fma2(acc[i][0], ap, b01.x); fma2(acc[i][1], ap, b01.y);
                    fma2(acc[i][2], ap, b23.x); fma2(acc[i][3], ap, b23.y);
                    fma2(acc[i][4], ap, b45.x); fma2(acc[i][5], ap, b45.y);
                    fma2(acc[i][6], ap, b67.x); fma2(acc[i][7], ap, b67.y);
                }
            }
        }
#pragma unroll
        for (int i = 0; i < 4; i++) {
            int r = tx + 32 * i;
            float* erow = sE + r * 129 + c1;
#pragma unroll
            for (int p = 0; p < 8; p++) {
                float2 v = upk(acc[i][p]);
                int j = c1 + 2 * p;
                erow[2 * p]     += v.x + sEB2[j];
                erow[2 * p + 1] += v.y + sEB2[j + 1];
            }
        }
    }
    __syncthreads();
    // LayerNorm + vector-atomic scatter (2 threads per edge row)
    {
        const int r = tid >> 1, half = tid & 1;
        const float* rowp = sE + r * 129 + half * 64;
        float s = 0.f, s2 = 0.f;
#pragma unroll 8
        for (int k = 0; k < 64; k++) { float t = rowp[k]; s += t; s2 = fmaf(t, t, s2); }
        s  += __shfl_xor_sync(0xffffffffu, s, 1);
        s2 += __shfl_xor_sync(0xffffffffu, s2, 1);
        const float mu  = s * 0.0078125f;
        const float var = fmaf(-mu, mu, s2 * 0.0078125f);
        const float rstd = rsqrtf(var + 1e-5f);
        const int e = e0 + r;
        float* outp = eout + (size_t)e * 128 + half * 64;
        const int cn = sCol[r];
        float4* aggp = (float4*)(g_agg + (size_t)cn * 128 + half * 64);
#pragma unroll
        for (int q = 0; q < 16; q++) {
            float v0 = rowp[4 * q], v1 = rowp[4 * q + 1];
            float v2 = rowp[4 * q + 2], v3 = rowp[4 * q + 3];
            atomicAdd(aggp + q, make_float4(v0, v1, v2, v3));
            int j = half * 64 + 4 * q;
            float4 o;
            o.x = fmaf((v0 - mu) * rstd, __ldg(ne_g + j),     __ldg(ne_b + j));
            o.y = fmaf((v1 - mu) * rstd, __ldg(ne_g + j + 1), __ldg(ne_b + j + 1));
            o.z = fmaf((v2 - mu) * rstd, __ldg(ne_g + j + 2), __ldg(ne_b + j + 2));
            o.w = fmaf((v3 - mu) * rstd, __ldg(ne_g + j + 3), __ldg(ne_b + j + 3));
            *(float4*)(outp + 4 * q) = o;
        }
        if (half == 0) atomicAdd(g_cnt + cn, 1.0f);
    }
}

// ------------------------------- kernel 3: nodes — R3 version -------------------
__global__ void __launch_bounds__(256, 1) k_node(
    const float* __restrict__ x, const float* __restrict__ nw1,
    const float* __restrict__ nb1, const float* __restrict__ nw2,
    const float* __restrict__ nb2, const float* __restrict__ nx_g,
    const float* __restrict__ nx_b, float* __restrict__ xout) {
    extern __shared__ float sm[];
    float* sX   = sm;            // 128*129 = 16512
    float* sA   = sm + 16512;    // 128*129 = 16512
    float* sW1h = sm + 33024;    // 128*64  = 8192 (reloaded between passes)
    float* sH   = sm + 41216;    // 128*65  = 8320
    float* sW2  = sm + 49536;    // 64*128  = 8192
    float* sNB2 = sm + 57728;    // 128
    const int tid = threadIdx.x;
    const int n0 = blockIdx.x * 128;

#pragma unroll
    for (int it = 0; it < 16; ++it) {
        int idx = tid + it * 256;
        int r = idx >> 5, q = idx & 31;
        int n = n0 + r;
        float4 v = make_float4(0.f, 0.f, 0.f, 0.f);
        float4 w = make_float4(0.f, 0.f, 0.f, 0.f);
        if (n < NN) {
            v = __ldg((const float4*)(x + (size_t)n * 128) + q);
            float c = g_cnt[n];
            float inv = 1.0f / fmaxf(c, 1.0f);
            float4 a = *((const float4*)(g_agg + (size_t)n * 128) + q);
            w = make_float4(a.x * inv, a.y * inv, a.z * inv, a.w * inv);
        }
        float* dx = sX + r * 129 + q * 4;
        dx[0] = v.x; dx[1] = v.y; dx[2] = v.z; dx[3] = v.w;
        float* da = sA + r * 129 + q * 4;
        da[0] = w.x; da[1] = w.y; da[2] = w.z; da[3] = w.w;
    }
    for (int idx = tid; idx < 8192; idx += 256) sW1h[idx] = __ldg(nw1 + idx);
    for (int idx = tid; idx < 8192; idx += 256) sW2[idx] = __ldg(nw2 + idx);
    if (tid < 128) sNB2[tid] = __ldg(nb2 + tid);
    __syncthreads();

    const int tx = tid & 31, ty = tid >> 5;
    const int c0 = ty * 8;
    u64t acc[4][4];
#pragma unroll
    for (int i = 0; i < 4; i++)
#pragma unroll
        for (int p = 0; p < 4; p++) acc[i][p] = 0ull;
    {
        const float* er[4];
#pragma unroll
        for (int i = 0; i < 4; i++) er[i] = sX + (tx + 32 * i) * 129;
#pragma unroll 4
        for (int k = 0; k < 128; k++) {
            const ulonglong2* bp = (const ulonglong2*)(sW1h + (k << 6) + c0);
            ulonglong2 b01 = bp[0], b23 = bp[1];
#pragma unroll
            for (int i = 0; i < 4; i++) {
                float a = er[i][k];
                u64t ap = pk2(a, a);
                fma2(acc[i][0], ap, b01.x); fma2(acc[i][1], ap, b01.y);
                fma2(acc[i][2], ap, b23.x); fma2(acc[i][3], ap, b23.y);
            }
        }
    }
    __syncthreads();
    for (int idx = tid; idx < 8192; idx += 256) sW1h[idx] = __ldg(nw1 + 8192 + idx);
    __syncthreads();
    {
        const float* er[4];
#pragma unroll
        for (int i = 0; i < 4; i++) er[i] = sA + (tx + 32 * i) * 129;
#pragma unroll 4
        for (int k = 0; k < 128; k++) {
            const ulonglong2* bp = (const ulonglong2*)(sW1h + (k << 6) + c0);
            ulonglong2 b01 = bp[0], b23 = bp[1];
#pragma unroll
            for (int i = 0; i < 4; i++) {
                float a = er[i][k];
                u64t ap = pk2(a, a);
                fma2(acc[i][0], ap, b01.x); fma2(acc[i][1], ap, b01.y);
                fma2(acc[i][2], ap, b23.x); fma2(acc[i][3], ap, b23.y);
            }
        }
    }
#pragma unroll
    for (int i = 0; i < 4; i++) {
        int r = tx + 32 * i;
        float* hd = sH + r * 65 + c0;
#pragma unroll
        for (int p = 0; p < 4; p++) {
            float2 v = upk(acc[i][p]);
            hd[2 * p]     = fmaxf(v.x + __ldg(nb1 + c0 + 2 * p), 0.f);
            hd[2 * p + 1] = fmaxf(v.y + __ldg(nb1 + c0 + 2 * p + 1), 0.f);
        }
    }
    __syncthreads();
    // stage 2
    {
        const int c1 = ty * 16;
        u64t acc2[4][8];
#pragma unroll
        for (int i = 0; i < 4; i++)
#pragma unroll
            for (int p = 0; p < 8; p++) acc2[i][p] = 0ull;
        const float* hr[4];
#pragma unroll
        for (int i = 0; i < 4; i++) hr[i] = sH + (tx + 32 * i) * 65;
#pragma unroll 4
        for (int k = 0; k < 64; k++) {
            const ulonglong2* bp = (const ulonglong2*)(sW2 + (k << 7) + c1);
            ulonglong2 b01 = bp[0], b23 = bp[1], b45 = bp[2], b67 = bp[3];
#pragma unroll
            for (int i = 0; i < 4; i++) {
                float a = hr[i][k];
                u64t ap = pk2(a, a);
                fma2(acc2[i][0], ap, b01.x); fma2(acc2[i][1], ap, b01.y);
                fma2(acc2[i][2], ap, b23.x); fma2(acc2[i][3], ap, b23.y);
                fma2(acc2[i][4], ap, b45.x); fma2(acc2[i][5], ap, b45.y);
                fma2(acc2[i][6], ap, b67.x); fma2(acc2[i][7], ap, b67.y);
            }
        }
#pragma unroll
        for (int i = 0; i < 4; i++) {
            int r = tx + 32 * i;
            float* xrow = sX + r * 129 + c1;
#pragma unroll
            for (int p = 0; p < 8; p++) {
                float2 v = upk(acc2[i][p]);
                int j = c1 + 2 * p;
                xrow[2 * p]     += v.x + sNB2[j];
                xrow[2 * p + 1] += v.y + sNB2[j + 1];
            }
        }
    }
    __syncthreads();
    // LayerNorm -> x_out
    {
        const int r = tid >> 1, half = tid & 1;
        const float* rowp = sX + r * 129 + half * 64;
        float s = 0.f, s2 = 0.f;
#pragma unroll 8
        for (int k = 0; k < 64; k++) { float t = rowp[k]; s += t; s2 = fmaf(t, t, s2); }
        s  += __shfl_xor_sync(0xffffffffu, s, 1);
        s2 += __shfl_xor_sync(0xffffffffu, s2, 1);
        const float mu  = s * 0.0078125f;
        const float var = fmaf(-mu, mu, s2 * 0.0078125f);
        const float rstd = rsqrtf(var + 1e-5f);
        const int n = n0 + r;
        if (n < NN) {
            float* outp = xout + (size_t)n * 128 + half * 64;
#pragma unroll
            for (int q = 0; q < 16; q++) {
                float v0 = rowp[4 * q], v1 = rowp[4 * q + 1];
                float v2 = rowp[4 * q + 2], v3 = rowp[4 * q + 3];
                int j = half * 64 + 4 * q;
                float4 o;
                o.x = fmaf((v0 - mu) * rstd, __ldg(nx_g + j),     __ldg(nx_b + j));
                o.y = fmaf((v1 - mu) * rstd, __ldg(nx_g + j + 1), __ldg(nx_b + j + 1));
                o.z = fmaf((v2 - mu) * rstd, __ldg(nx_g + j + 2), __ldg(nx_b + j + 2));
                o.w = fmaf((v3 - mu) * rstd, __ldg(nx_g + j + 3), __ldg(nx_b + j + 3));
                *(float4*)(outp + 4 * q) = o;
            }
        }
    }
}

// --------------------------------- launch ---------------------------------------
extern "C" void kernel_launch(void* const* d_in, const int* in_sizes, int n_in,
                              void* d_out, int out_size) {
    const float* x   = (const float*)d_in[0];
    const void*  ei  = d_in[1];               // int32 or int64 — detected on device
    const float* ea  = (const float*)d_in[2];
    const float* ew1 = (const float*)d_in[4];
    const float* eb1 = (const float*)d_in[5];
    const float* ew2 = (const float*)d_in[6];
    const float* eb2 = (const float*)d_in[7];
    const float* nw1 = (const float*)d_in[8];
    const float* nb1 = (const float*)d_in[9];
    const float* nw2 = (const float*)d_in[10];
    const float* nb2 = (const float*)d_in[11];
    const float* nxg = (const float*)d_in[12];
    const float* nxb = (const float*)d_in[13];
    const float* neg_ = (const float*)d_in[14];
    const float* neb_ = (const float*)d_in[15];
    float* xout = (float*)d_out;
    float* eout = xout + (size_t)NN * 128;

    const int SM_PRE  = 131584;              // (16384+16512)*4
    const int SM_EDGE = 41216 * 4 + 1536;    // 166400
    const int SM_NODE = 57728 * 4 + 512;     // 231424
    cudaFuncSetAttribute(k_pre,  cudaFuncAttributeMaxDynamicSharedMemorySize, SM_PRE);
    cudaFuncSetAttribute(k_edge, cudaFuncAttributeMaxDynamicSharedMemorySize, SM_EDGE);
    cudaFuncSetAttribute(k_node, cudaFuncAttributeMaxDynamicSharedMemorySize, SM_NODE);

    k_detect<<<1, 32>>>((const unsigned int*)ei);
    k_zero<<<1024, 256>>>();
    k_pre <<<(NN + 127) / 128, 256, SM_PRE>>>(x, ew1, eb1);
    k_edge<<<NE / 128, 256, SM_EDGE>>>(ea, ei, ew1, ew2, eb2, neg_, neb_, eout);
    k_node<<<(NN + 127) / 128, 256, SM_NODE>>>(x, nw1, nb1, nw2, nb2, nxg, nxb, xout);
}